// round 12
// baseline (speedup 1.0000x reference)
#include <cuda_runtime.h>

// ValueNorm: batch Welford (Chan merge) + normalize. HBM-bound.
// R12 = R10 config (592 CTAs, 4/SM) + dynamic work-stealing 32KB tiles in
// both phases (monotonic 64-bit ticket counters, replay-safe: each phase
// consumes exactly ntiles+NB tickets per replay). Ticket prefetch hides
// atomic latency. Kills the static-chunk straggler tail at the barrier.

#define NB 592            // 148 SMs * 4 CTAs/SM, all co-resident
#define NT 256
#define UNROLL 8
#define TILE ((long long)NT * UNROLL)   // 2048 float4 = 32KB
#define EPS 1e-5

__device__ double             g_psum[NB];
__device__ double             g_psq[NB];
__device__ unsigned           g_bar;    // barrier ticket counter (monotonic)
__device__ unsigned long long g_c1;     // phase-1 tile tickets (monotonic)
__device__ unsigned long long g_c2;     // phase-2 tile tickets (monotonic)

__global__ void __launch_bounds__(NT, 4)
vn_fused_kernel(const float* __restrict__ x, float* __restrict__ y,
                const float* __restrict__ count_p,
                const float* __restrict__ mean_p,
                const float* __restrict__ m2_p,
                float* __restrict__ out_tail,
                long long n)
{
    const int tid = threadIdx.x;
    const int bid = blockIdx.x;
    const long long n4 = n >> 2;
    const float4* __restrict__ x4 = (const float4*)x;
    float4* __restrict__ y4 = (float4*)y;

    const long long ntiles = n4 / TILE;
    const unsigned long long M = (unsigned long long)(ntiles + NB);

    __shared__ long long sh_t[2];
    __shared__ double sh_s[NT / 32];
    __shared__ double sh_q[NT / 32];
    const int wid = tid >> 5, lid = tid & 31;

    // ---------------- Phase 1: partial sum / sumsq, stolen tiles -----------
    float s = 0.0f, q = 0.0f;

    if (tid == 0)
        sh_t[0] = (long long)(atomicAdd(&g_c1, 1ULL) % M);
    __syncthreads();
    {
        int buf = 0;
        while (true) {
            long long t = sh_t[buf];
            if (t >= ntiles) break;
            if (tid == 0)   // prefetch next ticket while this tile streams
                sh_t[buf ^ 1] = (long long)(atomicAdd(&g_c1, 1ULL) % M);
            long long base = t * TILE + tid;
            float4 v[UNROLL];
            #pragma unroll
            for (int u = 0; u < UNROLL; ++u)
                v[u] = x4[base + (long long)u * NT];
            #pragma unroll
            for (int u = 0; u < UNROLL; ++u) {
                s += v[u].x + v[u].y + v[u].z + v[u].w;
                q += v[u].x * v[u].x + v[u].y * v[u].y
                   + v[u].z * v[u].z + v[u].w * v[u].w;
            }
            __syncthreads();
            buf ^= 1;
        }
    }
    // leftover float4s beyond tiled region (none for this shape, kept generic)
    long long done4 = ntiles * TILE;
    for (long long i = done4 + (long long)bid * NT + tid; i < n4;
         i += (long long)NB * NT) {
        float4 v = x4[i];
        s += v.x + v.y + v.z + v.w;
        q += v.x * v.x + v.y * v.y + v.z * v.z + v.w * v.w;
    }
    // scalar tail (none for this shape, kept generic)
    long long tail_base = n4 << 2;
    {
        long long gidx = (long long)bid * NT + tid;
        if (gidx < n - tail_base) {
            float v = x[tail_base + gidx];
            s += v; q += v * v;
        }
    }

    // block reduce (double)
    double ds = (double)s, dq = (double)q;
    #pragma unroll
    for (int o = 16; o > 0; o >>= 1) {
        ds += __shfl_down_sync(0xFFFFFFFFu, ds, o);
        dq += __shfl_down_sync(0xFFFFFFFFu, dq, o);
    }
    if (lid == 0) { sh_s[wid] = ds; sh_q[wid] = dq; }
    __syncthreads();

    // ---------------- Grid barrier (ticket-based, replay-safe) -------------
    if (tid == 0) {
        double ts = 0.0, tq = 0.0;
        #pragma unroll
        for (int w = 0; w < NT / 32; ++w) { ts += sh_s[w]; tq += sh_q[w]; }
        g_psum[bid] = ts;
        g_psq[bid]  = tq;
        __threadfence();
        unsigned ticket = atomicAdd(&g_bar, 1u);
        unsigned target = (ticket / NB + 1u) * NB;
        volatile unsigned* vb = &g_bar;
        while (*vb < target) __nanosleep(64);
        __threadfence();
    }
    __syncthreads();

    // -------- every CTA reduces all NB partials (deterministic order) ------
    {
        double ps = 0.0, pq = 0.0;
        for (int i = tid; i < NB; i += NT) {
            ps += g_psum[i];
            pq += g_psq[i];
        }
        #pragma unroll
        for (int o = 16; o > 0; o >>= 1) {
            ps += __shfl_down_sync(0xFFFFFFFFu, ps, o);
            pq += __shfl_down_sync(0xFFFFFFFFu, pq, o);
        }
        if (lid == 0) { sh_s[wid] = ps; sh_q[wid] = pq; }
        __syncthreads();
        if (tid == 0) {
            double ts = 0.0, tq = 0.0;
            #pragma unroll
            for (int w = 0; w < NT / 32; ++w) { ts += sh_s[w]; tq += sh_q[w]; }
            double dn    = (double)n;
            double bmean = ts / dn;
            double bm2   = tq - ts * ts / dn;
            double count = (double)*count_p;
            double mean  = (double)*mean_p;
            double m2    = (double)*m2_p;
            double new_count = count + dn;
            double delta     = bmean - mean;
            double new_mean  = mean + delta * dn / new_count;
            double new_m2    = m2 + bm2 + delta * delta * count * dn / new_count;
            double denom = new_count - 1.0;
            if (denom < 1.0) denom = 1.0;
            double std = sqrt(new_m2 / denom + (double)EPS);
            sh_s[0] = new_mean;
            sh_q[0] = 1.0 / std;
            if (bid == 0 && out_tail) {
                out_tail[0] = (float)new_count;
                out_tail[1] = (float)new_mean;
                out_tail[2] = (float)new_m2;
            }
        }
        __syncthreads();
    }
    const float shift = (float)sh_s[0];
    const float scale = (float)sh_q[0];
    __syncthreads();   // everyone has shift/scale before sh_t reuse

    // ---------------- Phase 2: normalize, stolen tiles ---------------------
    {
        long long gidx = (long long)bid * NT + tid;
        if (gidx < n - tail_base) {
            float v = x[tail_base + gidx];
            y[tail_base + gidx] = (v - shift) * scale;
        }
    }
    for (long long i = done4 + (long long)bid * NT + tid; i < n4;
         i += (long long)NB * NT) {
        float4 v = x4[i];
        v.x = (v.x - shift) * scale;
        v.y = (v.y - shift) * scale;
        v.z = (v.z - shift) * scale;
        v.w = (v.w - shift) * scale;
        __stcs(&y4[i], v);
    }

    if (tid == 0)
        sh_t[0] = (long long)(atomicAdd(&g_c2, 1ULL) % M);
    __syncthreads();
    {
        int buf = 0;
        while (true) {
            long long t = sh_t[buf];
            if (t >= ntiles) break;
            if (tid == 0)
                sh_t[buf ^ 1] = (long long)(atomicAdd(&g_c2, 1ULL) % M);
            long long base = t * TILE + tid;
            float4 v[UNROLL];
            #pragma unroll
            for (int u = 0; u < UNROLL; ++u)
                v[u] = x4[base + (long long)u * NT];
            #pragma unroll
            for (int u = 0; u < UNROLL; ++u) {
                v[u].x = (v[u].x - shift) * scale;
                v[u].y = (v[u].y - shift) * scale;
                v[u].z = (v[u].z - shift) * scale;
                v[u].w = (v[u].w - shift) * scale;
            }
            #pragma unroll
            for (int u = 0; u < UNROLL; ++u)
                __stcs(&y4[base + (long long)u * NT], v[u]);
            __syncthreads();
            buf ^= 1;
        }
    }
}

// ---------------------------------------------------------------------------
extern "C" void kernel_launch(void* const* d_in, const int* in_sizes, int n_in,
                              void* d_out, int out_size)
{
    const float* x       = (const float*)d_in[0];
    const float* count_p = (const float*)d_in[1];
    const float* mean_p  = (const float*)d_in[2];
    const float* m2_p    = (const float*)d_in[3];
    float* out = (float*)d_out;

    long long n = (long long)in_sizes[0];

    float* out_tail = nullptr;
    if ((long long)out_size >= n + 3) out_tail = out + n;

    vn_fused_kernel<<<NB, NT>>>(x, out, count_p, mean_p, m2_p, out_tail, n);
}

// round 13
// speedup vs baseline: 1.0219x; 1.0219x over previous
#include <cuda_runtime.h>

// ValueNorm: batch Welford (Chan merge) + normalize. HBM-bound.
// R13 = R10 (best: contiguous chunks, 592 CTAs, ticket barrier) + SMEM cache:
// each CTA keeps its first 11 float4-slots/thread (44KB) of x in shared
// memory across the barrier; phase 2 reads those from SMEM, cutting ~26MB
// (~10%) off the phase-2 global read stream. Only mechanism left that can
// reduce traffic (L2 reuse disproven in 4 attempts; smem survives phases).

#define NB 592            // 148 SMs * 4 CTAs/SM, all co-resident
#define NT 256
#define UNROLL 8
#define TILE ((long long)NT * UNROLL)   // 2048 float4 = 32KB
#define CACHE_SLOTS 11    // 11 float4/thread = 44KB/CTA in smem
#define EPS 1e-5

__device__ double   g_psum[NB];
__device__ double   g_psq[NB];
__device__ unsigned g_bar;   // monotonically increasing ticket counter

__global__ void __launch_bounds__(NT, 4)
vn_fused_kernel(const float* __restrict__ x, float* __restrict__ y,
                const float* __restrict__ count_p,
                const float* __restrict__ mean_p,
                const float* __restrict__ m2_p,
                float* __restrict__ out_tail,
                long long n)
{
    const int tid = threadIdx.x;
    const int bid = blockIdx.x;
    const long long n4 = n >> 2;
    const float4* __restrict__ x4 = (const float4*)x;
    float4* __restrict__ y4 = (float4*)y;

    __shared__ float4 buf[CACHE_SLOTS * NT];           // 44KB persists phases
    __shared__ double sh_s[NT / 32];
    __shared__ double sh_q[NT / 32];

    // contiguous tile-range per CTA (R10 layout)
    const long long ntiles = n4 / TILE;
    const long long base_t = ntiles / NB;
    const long long rem_t  = ntiles % NB;
    const long long t0   = (long long)bid * base_t + (bid < rem_t ? bid : rem_t);
    const long long tcnt = base_t + (bid < rem_t ? 1 : 0);

    // ---------------- Phase 1: partial sum / sumsq (ascending) -------------
    float s = 0.0f, q = 0.0f;
    for (long long k = 0; k < tcnt; ++k) {
        long long base = (t0 + k) * TILE + tid;
        float4 v[UNROLL];
        #pragma unroll
        for (int u = 0; u < UNROLL; ++u)
            v[u] = x4[base + (long long)u * NT];
        #pragma unroll
        for (int u = 0; u < UNROLL; ++u) {
            s += v[u].x + v[u].y + v[u].z + v[u].w;
            q += v[u].x * v[u].x + v[u].y * v[u].y
               + v[u].z * v[u].z + v[u].w * v[u].w;
        }
        if (k < (CACHE_SLOTS + UNROLL - 1) / UNROLL) {   // only first 2 tiles
            #pragma unroll
            for (int u = 0; u < UNROLL; ++u) {
                long long slot = k * UNROLL + u;
                if (slot < CACHE_SLOTS)
                    buf[slot * NT + tid] = v[u];
            }
        }
    }
    // leftover float4s beyond tiled region (none for this shape, kept generic)
    long long done4 = ntiles * TILE;
    for (long long i = done4 + (long long)bid * NT + tid; i < n4;
         i += (long long)NB * NT) {
        float4 v = x4[i];
        s += v.x + v.y + v.z + v.w;
        q += v.x * v.x + v.y * v.y + v.z * v.z + v.w * v.w;
    }
    // scalar tail (none for this shape, kept generic)
    long long tail_base = n4 << 2;
    {
        long long gidx = (long long)bid * NT + tid;
        if (gidx < n - tail_base) {
            float v = x[tail_base + gidx];
            s += v; q += v * v;
        }
    }

    // block reduce (double)
    double ds = (double)s, dq = (double)q;
    #pragma unroll
    for (int o = 16; o > 0; o >>= 1) {
        ds += __shfl_down_sync(0xFFFFFFFFu, ds, o);
        dq += __shfl_down_sync(0xFFFFFFFFu, dq, o);
    }
    int wid = tid >> 5, lid = tid & 31;
    if (lid == 0) { sh_s[wid] = ds; sh_q[wid] = dq; }
    __syncthreads();

    // ---------------- Grid barrier (ticket-based, replay-safe) -------------
    if (tid == 0) {
        double ts = 0.0, tq = 0.0;
        #pragma unroll
        for (int w = 0; w < NT / 32; ++w) { ts += sh_s[w]; tq += sh_q[w]; }
        g_psum[bid] = ts;
        g_psq[bid]  = tq;
        __threadfence();
        unsigned ticket = atomicAdd(&g_bar, 1u);
        unsigned target = (ticket / NB + 1u) * NB;
        volatile unsigned* vb = &g_bar;
        while (*vb < target) __nanosleep(64);
        __threadfence();
    }
    __syncthreads();

    // -------- every CTA reduces all NB partials (deterministic order) ------
    {
        double ps = 0.0, pq = 0.0;
        for (int i = tid; i < NB; i += NT) {
            ps += g_psum[i];
            pq += g_psq[i];
        }
        #pragma unroll
        for (int o = 16; o > 0; o >>= 1) {
            ps += __shfl_down_sync(0xFFFFFFFFu, ps, o);
            pq += __shfl_down_sync(0xFFFFFFFFu, pq, o);
        }
        if (lid == 0) { sh_s[wid] = ps; sh_q[wid] = pq; }
        __syncthreads();
        if (tid == 0) {
            double ts = 0.0, tq = 0.0;
            #pragma unroll
            for (int w = 0; w < NT / 32; ++w) { ts += sh_s[w]; tq += sh_q[w]; }
            double dn    = (double)n;
            double bmean = ts / dn;
            double bm2   = tq - ts * ts / dn;
            double count = (double)*count_p;
            double mean  = (double)*mean_p;
            double m2    = (double)*m2_p;
            double new_count = count + dn;
            double delta     = bmean - mean;
            double new_mean  = mean + delta * dn / new_count;
            double new_m2    = m2 + bm2 + delta * delta * count * dn / new_count;
            double denom = new_count - 1.0;
            if (denom < 1.0) denom = 1.0;
            double std = sqrt(new_m2 / denom + (double)EPS);
            sh_s[0] = new_mean;
            sh_q[0] = 1.0 / std;
            if (bid == 0 && out_tail) {
                out_tail[0] = (float)new_count;
                out_tail[1] = (float)new_mean;
                out_tail[2] = (float)new_m2;
            }
        }
        __syncthreads();
    }
    const float shift = (float)sh_s[0];
    const float scale = (float)sh_q[0];

    // ---------------- Phase 2: normalize own chunk (descending) ------------
    // Slots < CACHE_SLOTS come from SMEM (saved global reads).
    {
        long long gidx = (long long)bid * NT + tid;
        if (gidx < n - tail_base) {
            float v = x[tail_base + gidx];
            y[tail_base + gidx] = (v - shift) * scale;
        }
    }
    for (long long i = done4 + (long long)bid * NT + tid; i < n4;
         i += (long long)NB * NT) {
        float4 v = x4[i];
        v.x = (v.x - shift) * scale;
        v.y = (v.y - shift) * scale;
        v.z = (v.z - shift) * scale;
        v.w = (v.w - shift) * scale;
        __stcs(&y4[i], v);
    }

    for (long long k = tcnt - 1; k >= 0; --k) {
        long long base = (t0 + k) * TILE + tid;
        float4 v[UNROLL];
        const bool cached_tile = (k * UNROLL < CACHE_SLOTS);
        if (cached_tile) {
            #pragma unroll
            for (int u = 0; u < UNROLL; ++u) {
                long long slot = k * UNROLL + u;
                if (slot < CACHE_SLOTS)
                    v[u] = buf[slot * NT + tid];
                else
                    v[u] = x4[base + (long long)u * NT];
            }
        } else {
            #pragma unroll
            for (int u = 0; u < UNROLL; ++u)
                v[u] = x4[base + (long long)u * NT];
        }
        #pragma unroll
        for (int u = 0; u < UNROLL; ++u) {
            v[u].x = (v[u].x - shift) * scale;
            v[u].y = (v[u].y - shift) * scale;
            v[u].z = (v[u].z - shift) * scale;
            v[u].w = (v[u].w - shift) * scale;
        }
        #pragma unroll
        for (int u = 0; u < UNROLL; ++u)
            __stcs(&y4[base + (long long)u * NT], v[u]);
    }
}

// ---------------------------------------------------------------------------
extern "C" void kernel_launch(void* const* d_in, const int* in_sizes, int n_in,
                              void* d_out, int out_size)
{
    const float* x       = (const float*)d_in[0];
    const float* count_p = (const float*)d_in[1];
    const float* mean_p  = (const float*)d_in[2];
    const float* m2_p    = (const float*)d_in[3];
    float* out = (float*)d_out;

    long long n = (long long)in_sizes[0];

    float* out_tail = nullptr;
    if ((long long)out_size >= n + 3) out_tail = out + n;

    vn_fused_kernel<<<NB, NT>>>(x, out, count_p, mean_p, m2_p, out_tail, n);
}